// round 13
// baseline (speedup 1.0000x reference)
#include <cuda_runtime.h>
#include <cuda_bf16.h>
#include <cstdint>
#include <math.h>

#define NN 8192
#define DD 128
#define NTILE 64
#define TTOT (NTILE * NTILE)
#define NCTA 148
#define NTHR 512

#if defined(__CUDA_ARCH__) && \
    (defined(__CUDA_ARCH_FEAT_SM103_ALL) || defined(__CUDA_ARCH_FEAT_SM100_ALL) || \
     defined(__CUDA_ARCH_SPECIFIC__) || defined(__CUDA_ARCH_FAMILY_SPECIFIC__))
#define HAS_TCGEN05 1
#else
#define HAS_TCGEN05 0
#endif

// scale = sqrt(10/ln2) so MMA produces z = (10*log2 e) * dot directly
#define FSCALE 3.7982826f
#define C1F 14.4269504f          // 10*log2(e)
#define LN2F 0.69314718f
#define E10F 22026.4658f         // 2^C1 = e^10

// ---------------- scratch ----------------------------------------------------
__device__ __nv_bfloat16 g_hi[(size_t)NN * DD];
__device__ __nv_bfloat16 g_lo[(size_t)NN * DD];
__device__ float g_Te[NN], g_Te1[NN];
__device__ float g_fsA[DD], g_fs1[DD];
__device__ float g_part[8];
__device__ int g_ctr;

// ---------------- SMEM layout ------------------------------------------------
#define OFF_TMEM 0
#define OFF_MBAR0 8
#define OFF_LABF 1024          // float[4][128] = 2 KB
#define SM_AHI 4096
#define SM_ALO (SM_AHI + 32768)
#define SM_B0  (SM_ALO + 32768)
#define BSTRIDE 65536
#define SM_TOTAL (SM_B0 + 2 * BSTRIDE)   // 200704 B

#if HAS_TCGEN05
__device__ __forceinline__ uint32_t smem_u32(const void* p) {
    uint32_t a;
    asm("{ .reg .u64 t; cvta.to.shared.u64 t, %1; cvt.u32.u64 %0, t; }" : "=r"(a) : "l"(p));
    return a;
}
#define TCG_ALLOC(sm, n) asm volatile("tcgen05.alloc.cta_group::1.sync.aligned.shared::cta.b32 [%0], %1;" :: "r"(sm), "r"(n) : "memory")
#define TCG_DEALLOC(t, n) asm volatile("tcgen05.dealloc.cta_group::1.sync.aligned.b32 %0, %1;" :: "r"(t), "r"(n))
#define TCG_RELINQ() asm volatile("tcgen05.relinquish_alloc_permit.cta_group::1.sync.aligned;")
#define TCG_COMMIT(mb) asm volatile("tcgen05.commit.cta_group::1.mbarrier::arrive::one.shared::cluster.b64 [%0];" :: "r"(mb) : "memory")
#define TCG_WAIT_LD() asm volatile("tcgen05.wait::ld.sync.aligned;" ::: "memory")
#define TCG_FENCE_BEFORE() asm volatile("tcgen05.fence::before_thread_sync;" ::: "memory")
#define TCG_FENCE_AFTER() asm volatile("tcgen05.fence::after_thread_sync;" ::: "memory")
#define FENCE_ASYNC_SHARED() asm volatile("fence.proxy.async.shared::cta;" ::: "memory")
#define MBAR_INIT(mb, c) asm volatile("mbarrier.init.shared.b64 [%0], %1;" :: "r"(mb), "r"(c) : "memory")
#define MBAR_INVAL(mb) asm volatile("mbarrier.inval.shared.b64 [%0];" :: "r"(mb) : "memory")
#define CP_ASYNC16(dst, src) asm volatile("cp.async.cg.shared.global [%0], [%1], 16;" :: "r"(dst), "l"(src) : "memory")
#define CP_COMMIT() asm volatile("cp.async.commit_group;" ::: "memory")
#define CP_WAIT(n) asm volatile("cp.async.wait_group %0;" :: "n"(n) : "memory")

#define MBAR_WAIT(mb, ph) do { \
    uint32_t _m = (mb); uint32_t _p = (ph); uint32_t _d; \
    asm volatile("{ .reg .pred p; mbarrier.try_wait.parity.acquire.cta.shared::cta.b64 p, [%1], %2; selp.b32 %0,1,0,p; }" \
                 : "=r"(_d) : "r"(_m), "r"(_p) : "memory"); \
    if (!_d) { \
        asm volatile("{ .reg .pred P1; WL_%=: mbarrier.try_wait.parity.acquire.cta.shared::cta.b64 P1, [%0], %1, 0x989680; @P1 bra.uni WD_%=; bra.uni WL_%=; WD_%=: }" \
                     :: "r"(_m), "r"(_p) : "memory"); \
    } } while (0)

#define LDTM_X32(r, addr) \
    asm volatile("tcgen05.ld.sync.aligned.32x32b.x32.b32 " \
        "{%0,%1,%2,%3,%4,%5,%6,%7,%8,%9,%10,%11,%12,%13,%14,%15," \
        "%16,%17,%18,%19,%20,%21,%22,%23,%24,%25,%26,%27,%28,%29,%30,%31}, [%32];" \
        : "=r"((r)[0]),"=r"((r)[1]),"=r"((r)[2]),"=r"((r)[3]),"=r"((r)[4]),"=r"((r)[5]),"=r"((r)[6]),"=r"((r)[7]), \
          "=r"((r)[8]),"=r"((r)[9]),"=r"((r)[10]),"=r"((r)[11]),"=r"((r)[12]),"=r"((r)[13]),"=r"((r)[14]),"=r"((r)[15]), \
          "=r"((r)[16]),"=r"((r)[17]),"=r"((r)[18]),"=r"((r)[19]),"=r"((r)[20]),"=r"((r)[21]),"=r"((r)[22]),"=r"((r)[23]), \
          "=r"((r)[24]),"=r"((r)[25]),"=r"((r)[26]),"=r"((r)[27]),"=r"((r)[28]),"=r"((r)[29]),"=r"((r)[30]),"=r"((r)[31]) \
        : "r"(addr))

__device__ __forceinline__ void mma_f16_ss(uint32_t d, uint64_t a, uint64_t b,
                                           uint32_t idesc, uint32_t en) {
    asm volatile(
        "{\n\t.reg .pred p;\n\t"
        "setp.ne.u32 p, %5, 0;\n\t"
        "tcgen05.mma.cta_group::1.kind::f16 [%0], %1, %2, %3, {%4,%4,%4,%4}, p;\n\t}"
        :: "r"(d), "l"(a), "l"(b), "r"(idesc), "r"(0u), "r"(en) : "memory");
}

static constexpr uint64_t DESC_BASE =
    (uint64_t(2) << 61) | (uint64_t(1) << 46) | (uint64_t(64) << 32) | (uint64_t(1) << 16);
static constexpr uint32_t IDESC =
    (1u << 4) | (1u << 7) | (1u << 10) | ((128u / 8) << 17) | ((128u / 16) << 24);

__device__ __forceinline__ uint32_t tile_off(int row, int col) {
    uint32_t off = (uint32_t)((row >> 3) + ((col >> 6) << 4)) * 1024u
                 + (uint32_t)(row & 7) * 128u + (uint32_t)(col & 63) * 2u;
    return off ^ ((off >> 3) & 0x70);
}

__device__ __forceinline__ float fast_ex2(float x) {
    float r; asm("ex2.approx.f32 %0, %1;" : "=f"(r) : "f"(x)); return r;
}

#define PK2(d, lo, hi)  asm("mov.b64 %0, {%1,%2};" : "=l"(d) : "r"(__float_as_uint(lo)), "r"(__float_as_uint(hi)))
#define UPK2(lo, hi, s) asm("mov.b64 {%0,%1}, %2;" : "=r"(lo), "=r"(hi) : "l"(s))
#define ADD2(d, a, b)   asm("add.rn.f32x2 %0, %1, %2;" : "=l"(d) : "l"(a), "l"(b))
#define FMA2(d, a, b, c) asm("fma.rn.f32x2 %0, %1, %2, %3;" : "=l"(d) : "l"(a), "l"(b), "l"(c))
#endif  // HAS_TCGEN05

// ---------------------------------------------------------------------------
// Split (FSCALE * x) into bf16 hi/lo
// ---------------------------------------------------------------------------
__global__ __launch_bounds__(256)
void k_convert(const float* __restrict__ f) {
    int idx = blockIdx.x * 256 + threadIdx.x;
    if (idx < NN * DD / 4) {
        float4 v = ((const float4*)f)[idx];
        v.x *= FSCALE; v.y *= FSCALE; v.z *= FSCALE; v.w *= FSCALE;
        __nv_bfloat16 h0 = __float2bfloat16(v.x), h1 = __float2bfloat16(v.y);
        __nv_bfloat16 h2 = __float2bfloat16(v.z), h3 = __float2bfloat16(v.w);
        __nv_bfloat162* hp = (__nv_bfloat162*)(g_hi + (size_t)idx * 4);
        __nv_bfloat162* lp = (__nv_bfloat162*)(g_lo + (size_t)idx * 4);
        hp[0] = __nv_bfloat162(h0, h1);
        hp[1] = __nv_bfloat162(h2, h3);
        lp[0] = __nv_bfloat162(__float2bfloat16(v.x - __bfloat162float(h0)),
                               __float2bfloat16(v.y - __bfloat162float(h1)));
        lp[1] = __nv_bfloat162(__float2bfloat16(v.z - __bfloat162float(h2)),
                               __float2bfloat16(v.w - __bfloat162float(h3)));
    }
}

// ---------------------------------------------------------------------------
// k_fsum: column sums of feats (all rows, and label==1 rows). Grid 16 x 512.
// thread (d = tid&127, rg = tid>>7) sums 128 rows.
// ---------------------------------------------------------------------------
__global__ __launch_bounds__(512)
void k_fsum(const float* __restrict__ f, const int* __restrict__ labels) {
    __shared__ float sA[512], s1[512];
    const int tid = threadIdx.x;
    const int d = tid & 127, rg = tid >> 7;
    const int r0 = blockIdx.x * 512 + rg * 128;
    float a = 0.0f, b = 0.0f;
#pragma unroll 4
    for (int r = 0; r < 128; r++) {
        float v = f[(size_t)(r0 + r) * DD + d];
        float w = (float)labels[r0 + r];
        a += v;
        b = fmaf(w, v, b);
    }
    sA[tid] = a; s1[tid] = b;
    __syncthreads();
    if (tid < 128) {
        float ta = sA[tid] + sA[tid + 128] + sA[tid + 256] + sA[tid + 384];
        float tb = s1[tid] + s1[tid + 128] + s1[tid + 256] + s1[tid + 384];
        atomicAdd(&g_fsA[tid], ta);
        atomicAdd(&g_fs1[tid], tb);
    }
}

// ---------------------------------------------------------------------------
// k_tiles: persistent 148-CTA schedule, 512 threads, cp.async 2-ahead,
// ping-pong TMEM. MMA gives z = C1*dot. Epilogue accumulates only
// Te = sum 2^z and Te1 = sum w*2^z (scale 2^C1 folded out in k_final).
// ---------------------------------------------------------------------------
__global__ __launch_bounds__(NTHR, 1)
void k_tiles(const int* __restrict__ labels) {
#if HAS_TCGEN05
    extern __shared__ char smem[];
    const uint32_t sb = smem_u32(smem);
    const int tid = threadIdx.x;
    const int cta = blockIdx.x;

    const int t0 = (TTOT * cta) / NCTA;
    const int t1 = (TTOT * (cta + 1)) / NCTA;
    const int len = t1 - t0;

    if (tid == 0) { MBAR_INIT(sb + OFF_MBAR0, 1); MBAR_INIT(sb + OFF_MBAR0 + 8, 1); }
    if (tid < 32) { TCG_ALLOC(sb + OFF_TMEM, 256); TCG_RELINQ(); }
    __syncthreads();
    uint32_t tmem;
    asm volatile("ld.shared.b32 %0, [%1];" : "=r"(tmem) : "r"(sb + OFF_TMEM));

    const int lrow = tid >> 2, lq = tid & 3;

#define LOADA(ii) do { \
        const uint4* _ah = (const uint4*)(g_hi + (size_t)((ii) * 128 + lrow) * DD + lq * 32); \
        const uint4* _al = (const uint4*)(g_lo + (size_t)((ii) * 128 + lrow) * DD + lq * 32); \
        _Pragma("unroll") \
        for (int _c = 0; _c < 4; _c++) { \
            uint32_t _o = tile_off(lrow, lq * 32 + _c * 8); \
            *(uint4*)(smem + SM_AHI + _o) = _ah[_c]; \
            *(uint4*)(smem + SM_ALO + _o) = _al[_c]; \
        } } while (0)

#define CPLOADB(k) do { \
        int _jb = ((t0 + (k)) & 63) * 128; \
        const char* _sh = (const char*)(g_hi + (size_t)(_jb + lrow) * DD + lq * 32); \
        const char* _sl = (const char*)(g_lo + (size_t)(_jb + lrow) * DD + lq * 32); \
        uint32_t _bb = sb + SM_B0 + ((k) & 1) * BSTRIDE; \
        _Pragma("unroll") \
        for (int _c = 0; _c < 4; _c++) { \
            uint32_t _o = tile_off(lrow, lq * 32 + _c * 8); \
            CP_ASYNC16(_bb + _o, _sh + _c * 16); \
            CP_ASYNC16(_bb + 32768 + _o, _sl + _c * 16); \
        } \
        CP_COMMIT(); \
    } while (0)

#define LABLOAD(k) do { \
        if (tid < 128) { \
            int _jb = ((t0 + (k)) & 63) * 128; \
            ((float*)(smem + OFF_LABF))[((k) & 3) * 128 + tid] = (float)__ldg(&labels[_jb + tid]); \
        } } while (0)

#define ISSUE(k) do { \
        uint32_t _dtm = tmem + ((k) & 1) * 128; \
        uint32_t _bb = sb + SM_B0 + ((k) & 1) * BSTRIDE; \
        uint64_t _bH = DESC_BASE | ((uint64_t)(_bb >> 4) & 0x3FFF); \
        uint64_t _bL = DESC_BASE | ((uint64_t)((_bb + 32768) >> 4) & 0x3FFF); \
        uint64_t _aH = DESC_BASE | ((uint64_t)((sb + SM_AHI) >> 4) & 0x3FFF); \
        uint64_t _aL = DESC_BASE | ((uint64_t)((sb + SM_ALO) >> 4) & 0x3FFF); \
        const uint64_t _offs[8] = {0, 2, 4, 6, 1024, 1026, 1028, 1030}; \
        uint32_t _en = 0; \
        _Pragma("unroll") \
        for (int _k = 0; _k < 8; _k++) { mma_f16_ss(_dtm, _aH + _offs[_k], _bH + _offs[_k], IDESC, _en); _en = 1; } \
        _Pragma("unroll") \
        for (int _k = 0; _k < 8; _k++) mma_f16_ss(_dtm, _aH + _offs[_k], _bL + _offs[_k], IDESC, 1); \
        _Pragma("unroll") \
        for (int _k = 0; _k < 8; _k++) mma_f16_ss(_dtm, _aL + _offs[_k], _bH + _offs[_k], IDESC, 1); \
        TCG_COMMIT(sb + OFF_MBAR0 + ((k) & 1) * 8); \
    } while (0)

    int aI = t0 >> 6;
    LOADA(aI);
    CPLOADB(0); LABLOAD(0);
    CPLOADB(1); LABLOAD(1);
    CP_WAIT(1);
    __syncthreads();
    if (tid == 0) { FENCE_ASYNC_SHARED(); ISSUE(0); }

    const int row = tid & 127;
    const int colBase = (tid >> 7) * 32;

    int epiI = aI;
    int gRow = epiI * 128 + row;
    unsigned long long Te = 0, Te1 = 0;

#define FLUSH() do { \
        uint32_t _l, _h; float _a; \
        UPK2(_l, _h, Te);  _a = __uint_as_float(_l) + __uint_as_float(_h); atomicAdd(&g_Te[gRow], _a); \
        UPK2(_l, _h, Te1); _a = __uint_as_float(_l) + __uint_as_float(_h); atomicAdd(&g_Te1[gRow], _a); \
    } while (0)

    for (int k = 0; k < len; k++) {
        MBAR_WAIT(sb + OFF_MBAR0 + (k & 1) * 8, (k >> 1) & 1);
        TCG_FENCE_AFTER();

        const bool pref = (k + 2 < len);
        if (pref) { CPLOADB(k + 2); LABLOAD(k + 2); }
        if (k + 1 < len) {
            int ni = (t0 + k + 1) >> 6;
            if (ni != aI) { LOADA(ni); aI = ni; }
            if (pref) CP_WAIT(1); else CP_WAIT(0);
            __syncthreads();
            if (tid == 0) { FENCE_ASYNC_SHARED(); ISSUE(k + 1); }
        }

        const int ei = (t0 + k) >> 6;
        if (ei != epiI) {
            FLUSH();
            Te = Te1 = 0;
            epiI = ei;
            gRow = epiI * 128 + row;
        }

        uint32_t r0[32];
        LDTM_X32(r0, tmem + (k & 1) * 128 + colBase);
        TCG_WAIT_LD();

        const uint32_t lA = sb + OFF_LABF + (k & 3) * 512 + colBase * 4;
#pragma unroll
        for (int p = 0; p < 16; p++) {
            float e0 = fast_ex2(__uint_as_float(r0[2 * p]));
            float e1 = fast_ex2(__uint_as_float(r0[2 * p + 1]));
            unsigned long long pe, pw;
            PK2(pe, e0, e1);
            asm("ld.shared.b64 %0, [%1];" : "=l"(pw) : "r"(lA + p * 8));
            ADD2(Te, Te, pe);
            FMA2(Te1, pw, pe, Te1);
        }
        TCG_FENCE_BEFORE();
    }
    FLUSH();

    __syncthreads();
    if (tid == 0) { MBAR_INVAL(sb + OFF_MBAR0); MBAR_INVAL(sb + OFF_MBAR0 + 8); }
    __syncthreads();
    if (tid < 32) TCG_DEALLOC(tmem, 256);
#undef LOADA
#undef CPLOADB
#undef LABLOAD
#undef ISSUE
#undef FLUSH
#endif  // HAS_TCGEN05
}

// ---------------------------------------------------------------------------
// k_final (8 CTAs, last-block combine):
//   Td  = C1*dot(f_i, fsumAll); Td1 = C1*dot(f_i, fsum1)  [row sums of z]
//   sameE_s = lab? Te1 : Te-Te1 ; neg_s = Te - sameE_s ; S1_s = sameE_s - 2^C1
//   posZ = (lab? Td1 : Td-Td1) - C1 ; cnt = lab? n1-1 : NN-n1-1
//   posD = ln2*posZ - 10*cnt ; lsum = cnt*(log(neg_s)-10) + S1_s/neg_s
// ---------------------------------------------------------------------------
__global__ __launch_bounds__(1024)
void k_final(const float* __restrict__ f, const int* __restrict__ labels,
             float* __restrict__ out) {
    const int tid = threadIdx.x;
    __shared__ int sN[1024];
    __shared__ float sS[1024];
    __shared__ float fsA[DD], fs1[DD];

    if (tid < DD) { fsA[tid] = g_fsA[tid]; fs1[tid] = g_fs1[tid]; }

    int ln = 0;
#pragma unroll
    for (int it = 0; it < NN / 1024; it++) ln += labels[it * 1024 + tid];
    sN[tid] = ln;
    __syncthreads();
    for (int k = 512; k > 0; k >>= 1) {
        if (tid < k) sN[tid] += sN[tid + k];
        __syncthreads();
    }
    const int n1 = sN[0];

    const int i = blockIdx.x * 1024 + tid;
    const int lab = labels[i];

    // two D=128 dots
    float dA = 0.0f, d1 = 0.0f;
    const float4* fi = (const float4*)(f + (size_t)i * DD);
#pragma unroll
    for (int c = 0; c < 32; c++) {
        float4 v = fi[c];
        dA = fmaf(v.x, fsA[4 * c + 0], dA); d1 = fmaf(v.x, fs1[4 * c + 0], d1);
        dA = fmaf(v.y, fsA[4 * c + 1], dA); d1 = fmaf(v.y, fs1[4 * c + 1], d1);
        dA = fmaf(v.z, fsA[4 * c + 2], dA); d1 = fmaf(v.z, fs1[4 * c + 2], d1);
        dA = fmaf(v.w, fsA[4 * c + 3], dA); d1 = fmaf(v.w, fs1[4 * c + 3], d1);
    }
    float Td = C1F * dA, Td1 = C1F * d1;

    float Te = g_Te[i], Te1 = g_Te1[i];
    float sameE = lab ? Te1 : Te - Te1;
    float sameZ = lab ? Td1 : Td - Td1;
    float S1 = sameE - E10F;
    float posZ = sameZ - C1F;
    float neg = Te - sameE;
    float cnt = (float)(lab ? (n1 - 1) : (NN - n1 - 1));
    float posD = LN2F * posZ - 10.0f * cnt;
    float lsum = cnt * (__logf(neg) - 10.0f) + S1 / neg;
    sS[tid] = (posD - lsum) / cnt;
    __syncthreads();
    for (int k = 512; k > 0; k >>= 1) {
        if (tid < k) sS[tid] += sS[tid + k];
        __syncthreads();
    }
    if (tid == 0) {
        g_part[blockIdx.x] = sS[0];
        __threadfence();
        int old = atomicAdd(&g_ctr, 1);
        if (old == 7) {
            float s = 0.0f;
#pragma unroll
            for (int b = 0; b < 8; b++) s += g_part[b];
            out[0] = -(0.1f / 0.07f) * s / (float)NN;
        }
    }
}

// ---------------------------------------------------------------------------
extern "C" void kernel_launch(void* const* d_in, const int* in_sizes, int n_in,
                              void* d_out, int out_size) {
    const float* feats = (const float*)d_in[0];
    const int* labels = (const int*)d_in[1];
    float* out = (float*)d_out;

    void* p;
    cudaGetSymbolAddress(&p, g_Te);  cudaMemsetAsync(p, 0, NN * sizeof(float));
    cudaGetSymbolAddress(&p, g_Te1); cudaMemsetAsync(p, 0, NN * sizeof(float));
    cudaGetSymbolAddress(&p, g_fsA); cudaMemsetAsync(p, 0, DD * sizeof(float));
    cudaGetSymbolAddress(&p, g_fs1); cudaMemsetAsync(p, 0, DD * sizeof(float));
    cudaGetSymbolAddress(&p, g_ctr); cudaMemsetAsync(p, 0, sizeof(int));

    cudaFuncSetAttribute(k_tiles, cudaFuncAttributeMaxDynamicSharedMemorySize, SM_TOTAL);

    k_convert<<<(NN * DD / 4 + 255) / 256, 256>>>(feats);
    k_fsum<<<16, 512>>>(feats, labels);
    k_tiles<<<NCTA, NTHR, SM_TOTAL>>>(labels);
    k_final<<<8, 1024>>>(feats, labels, out);
}

// round 15
// speedup vs baseline: 1.1583x; 1.1583x over previous
#include <cuda_runtime.h>
#include <cuda_bf16.h>
#include <cstdint>
#include <math.h>

#define NN 8192
#define DD 128
#define NTILE 64
#define TTOT (NTILE * NTILE)
#define NCTA 148
#define NTHR 512

#if defined(__CUDA_ARCH__) && \
    (defined(__CUDA_ARCH_FEAT_SM103_ALL) || defined(__CUDA_ARCH_FEAT_SM100_ALL) || \
     defined(__CUDA_ARCH_SPECIFIC__) || defined(__CUDA_ARCH_FAMILY_SPECIFIC__))
#define HAS_TCGEN05 1
#else
#define HAS_TCGEN05 0
#endif

#define FSCALE 3.7982826f        // sqrt(10/ln2): MMA emits z = C1*dot
#define C1F 14.4269504f          // 10*log2(e)
#define LN2F 0.69314718f
#define E10F 22026.4658f         // 2^C1 = e^10

// ---------------- scratch: bf16 tiles + ONE zeroed block --------------------
__device__ __nv_bfloat16 g_hi[(size_t)NN * DD];
__device__ __nv_bfloat16 g_lo[(size_t)NN * DD];
// g_Z layout: [0,NN)=Te  [NN,2NN)=Te1  [2NN,+128)=fsA  [+128,+256)=fs1
//             [+256,+288)=part[32]  [+288]=ctr(int)  [+289]=n1(int)
#define ZOFF_TE   0
#define ZOFF_TE1  NN
#define ZOFF_FSA  (2 * NN)
#define ZOFF_FS1  (2 * NN + 128)
#define ZOFF_PART (2 * NN + 256)
#define ZOFF_CTR  (2 * NN + 288)
#define ZOFF_N1   (2 * NN + 289)
#define ZTOT      (2 * NN + 320)
__device__ float g_Z[ZTOT];

// ---------------- SMEM layout (k_tiles): B only, A lives in TMEM ------------
#define OFF_TMEM 0
#define OFF_MBAR0 8
#define OFF_LABF 1024          // float[4][128] = 2 KB
#define SM_B0 4096
#define BSTRIDE 65536          // per stage: BHI(32K)+BLO(32K)
#define SM_TOTAL (SM_B0 + 2 * BSTRIDE)   // 135168 B

#if HAS_TCGEN05
__device__ __forceinline__ uint32_t smem_u32(const void* p) {
    uint32_t a;
    asm("{ .reg .u64 t; cvta.to.shared.u64 t, %1; cvt.u32.u64 %0, t; }" : "=r"(a) : "l"(p));
    return a;
}
#define TCG_ALLOC(sm, n) asm volatile("tcgen05.alloc.cta_group::1.sync.aligned.shared::cta.b32 [%0], %1;" :: "r"(sm), "r"(n) : "memory")
#define TCG_DEALLOC(t, n) asm volatile("tcgen05.dealloc.cta_group::1.sync.aligned.b32 %0, %1;" :: "r"(t), "r"(n))
#define TCG_RELINQ() asm volatile("tcgen05.relinquish_alloc_permit.cta_group::1.sync.aligned;")
#define TCG_COMMIT(mb) asm volatile("tcgen05.commit.cta_group::1.mbarrier::arrive::one.shared::cluster.b64 [%0];" :: "r"(mb) : "memory")
#define TCG_WAIT_LD() asm volatile("tcgen05.wait::ld.sync.aligned;" ::: "memory")
#define TCG_WAIT_ST() asm volatile("tcgen05.wait::st.sync.aligned;" ::: "memory")
#define TCG_FENCE_BEFORE() asm volatile("tcgen05.fence::before_thread_sync;" ::: "memory")
#define TCG_FENCE_AFTER() asm volatile("tcgen05.fence::after_thread_sync;" ::: "memory")
#define FENCE_ASYNC_SHARED() asm volatile("fence.proxy.async.shared::cta;" ::: "memory")
#define MBAR_INIT(mb, c) asm volatile("mbarrier.init.shared.b64 [%0], %1;" :: "r"(mb), "r"(c) : "memory")
#define MBAR_INVAL(mb) asm volatile("mbarrier.inval.shared.b64 [%0];" :: "r"(mb) : "memory")
#define CP_ASYNC16(dst, src) asm volatile("cp.async.cg.shared.global [%0], [%1], 16;" :: "r"(dst), "l"(src) : "memory")
#define CP_COMMIT() asm volatile("cp.async.commit_group;" ::: "memory")
#define CP_WAIT(n) asm volatile("cp.async.wait_group %0;" :: "n"(n) : "memory")

#define MBAR_WAIT(mb, ph) do { \
    uint32_t _m = (mb); uint32_t _p = (ph); uint32_t _d; \
    asm volatile("{ .reg .pred p; mbarrier.try_wait.parity.acquire.cta.shared::cta.b64 p, [%1], %2; selp.b32 %0,1,0,p; }" \
                 : "=r"(_d) : "r"(_m), "r"(_p) : "memory"); \
    if (!_d) { \
        asm volatile("{ .reg .pred P1; WL_%=: mbarrier.try_wait.parity.acquire.cta.shared::cta.b64 P1, [%0], %1, 0x989680; @P1 bra.uni WD_%=; bra.uni WL_%=; WD_%=: }" \
                     :: "r"(_m), "r"(_p) : "memory"); \
    } } while (0)

#define LDTM_X32(r, addr) \
    asm volatile("tcgen05.ld.sync.aligned.32x32b.x32.b32 " \
        "{%0,%1,%2,%3,%4,%5,%6,%7,%8,%9,%10,%11,%12,%13,%14,%15," \
        "%16,%17,%18,%19,%20,%21,%22,%23,%24,%25,%26,%27,%28,%29,%30,%31}, [%32];" \
        : "=r"((r)[0]),"=r"((r)[1]),"=r"((r)[2]),"=r"((r)[3]),"=r"((r)[4]),"=r"((r)[5]),"=r"((r)[6]),"=r"((r)[7]), \
          "=r"((r)[8]),"=r"((r)[9]),"=r"((r)[10]),"=r"((r)[11]),"=r"((r)[12]),"=r"((r)[13]),"=r"((r)[14]),"=r"((r)[15]), \
          "=r"((r)[16]),"=r"((r)[17]),"=r"((r)[18]),"=r"((r)[19]),"=r"((r)[20]),"=r"((r)[21]),"=r"((r)[22]),"=r"((r)[23]), \
          "=r"((r)[24]),"=r"((r)[25]),"=r"((r)[26]),"=r"((r)[27]),"=r"((r)[28]),"=r"((r)[29]),"=r"((r)[30]),"=r"((r)[31]) \
        : "r"(addr))

#define STTM_X32(addr, r) \
    asm volatile("tcgen05.st.sync.aligned.32x32b.x32.b32 [%0], " \
        "{%1,%2,%3,%4,%5,%6,%7,%8,%9,%10,%11,%12,%13,%14,%15,%16," \
        "%17,%18,%19,%20,%21,%22,%23,%24,%25,%26,%27,%28,%29,%30,%31,%32};" \
        :: "r"(addr), \
           "r"((r)[0]),"r"((r)[1]),"r"((r)[2]),"r"((r)[3]),"r"((r)[4]),"r"((r)[5]),"r"((r)[6]),"r"((r)[7]), \
           "r"((r)[8]),"r"((r)[9]),"r"((r)[10]),"r"((r)[11]),"r"((r)[12]),"r"((r)[13]),"r"((r)[14]),"r"((r)[15]), \
           "r"((r)[16]),"r"((r)[17]),"r"((r)[18]),"r"((r)[19]),"r"((r)[20]),"r"((r)[21]),"r"((r)[22]),"r"((r)[23]), \
           "r"((r)[24]),"r"((r)[25]),"r"((r)[26]),"r"((r)[27]),"r"((r)[28]),"r"((r)[29]),"r"((r)[30]),"r"((r)[31]) \
        : "memory")

// TS-mode bf16 MMA: A in TMEM, B via smem descriptor
__device__ __forceinline__ void mma_f16_ts(uint32_t d, uint32_t a, uint64_t b,
                                           uint32_t idesc, uint32_t en) {
    asm volatile(
        "{\n\t.reg .pred p;\n\t"
        "setp.ne.u32 p, %5, 0;\n\t"
        "tcgen05.mma.cta_group::1.kind::f16 [%0], [%1], %2, %3, {%4,%4,%4,%4}, p;\n\t}"
        :: "r"(d), "r"(a), "l"(b), "r"(idesc), "r"(0u), "r"(en) : "memory");
}

static constexpr uint64_t DESC_BASE =
    (uint64_t(2) << 61) | (uint64_t(1) << 46) | (uint64_t(64) << 32) | (uint64_t(1) << 16);
static constexpr uint32_t IDESC =
    (1u << 4) | (1u << 7) | (1u << 10) | ((128u / 8) << 17) | ((128u / 16) << 24);

__device__ __forceinline__ uint32_t tile_off(int row, int col) {
    uint32_t off = (uint32_t)((row >> 3) + ((col >> 6) << 4)) * 1024u
                 + (uint32_t)(row & 7) * 128u + (uint32_t)(col & 63) * 2u;
    return off ^ ((off >> 3) & 0x70);
}

__device__ __forceinline__ float fast_ex2(float x) {
    float r; asm("ex2.approx.f32 %0, %1;" : "=f"(r) : "f"(x)); return r;
}

#define PK2(d, lo, hi)  asm("mov.b64 %0, {%1,%2};" : "=l"(d) : "r"(__float_as_uint(lo)), "r"(__float_as_uint(hi)))
#define UPK2(lo, hi, s) asm("mov.b64 {%0,%1}, %2;" : "=r"(lo), "=r"(hi) : "l"(s))
#define ADD2(d, a, b)   asm("add.rn.f32x2 %0, %1, %2;" : "=l"(d) : "l"(a), "l"(b))
#define FMA2(d, a, b, c) asm("fma.rn.f32x2 %0, %1, %2, %3;" : "=l"(d) : "l"(a), "l"(b), "l"(c))
#endif  // HAS_TCGEN05

// ---------------------------------------------------------------------------
// k_prep: one pass over feats. Per block: 64 rows. Produces
//  - g_hi/g_lo (FSCALE*x split to bf16 hi/lo)
//  - column sums fsA (all rows), fs1 (label==1 rows)  [raw, unscaled]
//  - n1 = total label count
// ---------------------------------------------------------------------------
__global__ __launch_bounds__(256)
void k_prep(const float* __restrict__ f, const int* __restrict__ labels) {
    __shared__ float sA[128], s1[128];
    __shared__ int sn;
    const int tid = threadIdx.x;
    if (tid < 128) { sA[tid] = 0.0f; s1[tid] = 0.0f; }
    if (tid == 0) sn = 0;
    __syncthreads();

    const int rbase = blockIdx.x * 64;
    const int c4 = (tid & 31) * 4;
    const int rg = tid >> 5;            // warp id: rows rbase+rg*8 .. +7
    float aA0 = 0, aA1 = 0, aA2 = 0, aA3 = 0;
    float a10 = 0, a11 = 0, a12 = 0, a13 = 0;

#pragma unroll
    for (int it = 0; it < 8; it++) {
        const int row = rbase + rg * 8 + it;
        float4 v = *(const float4*)(f + (size_t)row * DD + c4);
        float w = (float)labels[row];   // uniform per warp
        aA0 += v.x; aA1 += v.y; aA2 += v.z; aA3 += v.w;
        a10 = fmaf(w, v.x, a10); a11 = fmaf(w, v.y, a11);
        a12 = fmaf(w, v.z, a12); a13 = fmaf(w, v.w, a13);

        float sx = v.x * FSCALE, sy = v.y * FSCALE, sz = v.z * FSCALE, sw = v.w * FSCALE;
        __nv_bfloat16 h0 = __float2bfloat16(sx), h1 = __float2bfloat16(sy);
        __nv_bfloat16 h2 = __float2bfloat16(sz), h3 = __float2bfloat16(sw);
        __nv_bfloat162* hp = (__nv_bfloat162*)(g_hi + (size_t)row * DD + c4);
        __nv_bfloat162* lp = (__nv_bfloat162*)(g_lo + (size_t)row * DD + c4);
        hp[0] = __nv_bfloat162(h0, h1);
        hp[1] = __nv_bfloat162(h2, h3);
        lp[0] = __nv_bfloat162(__float2bfloat16(sx - __bfloat162float(h0)),
                               __float2bfloat16(sy - __bfloat162float(h1)));
        lp[1] = __nv_bfloat162(__float2bfloat16(sz - __bfloat162float(h2)),
                               __float2bfloat16(sw - __bfloat162float(h3)));
    }
    atomicAdd(&sA[c4 + 0], aA0); atomicAdd(&sA[c4 + 1], aA1);
    atomicAdd(&sA[c4 + 2], aA2); atomicAdd(&sA[c4 + 3], aA3);
    atomicAdd(&s1[c4 + 0], a10); atomicAdd(&s1[c4 + 1], a11);
    atomicAdd(&s1[c4 + 2], a12); atomicAdd(&s1[c4 + 3], a13);
    if (tid < 64) atomicAdd(&sn, labels[rbase + tid]);
    __syncthreads();
    if (tid < 128) {
        atomicAdd(&g_Z[ZOFF_FSA + tid], sA[tid]);
        atomicAdd(&g_Z[ZOFF_FS1 + tid], s1[tid]);
    }
    if (tid == 0) atomicAdd((int*)&g_Z[ZOFF_N1], sn);
}

// ---------------------------------------------------------------------------
// k_tiles: persistent 148-CTA schedule, 512 thr, TS-mode MMA (A in TMEM),
// cp.async 2-ahead B, ping-pong D in TMEM. Epilogue: Te = sum 2^z,
// Te1 = sum w*2^z per row.
// TMEM: D0 @0, D1 @128, Ahi @256 (64 cols), Alo @320 (64 cols).
// ---------------------------------------------------------------------------
__global__ __launch_bounds__(NTHR, 1)
void k_tiles(const int* __restrict__ labels) {
#if HAS_TCGEN05
    extern __shared__ char smem[];
    const uint32_t sb = smem_u32(smem);
    const int tid = threadIdx.x;
    const int cta = blockIdx.x;

    const int t0 = (TTOT * cta) / NCTA;
    const int t1 = (TTOT * (cta + 1)) / NCTA;
    const int len = t1 - t0;

    if (tid == 0) { MBAR_INIT(sb + OFF_MBAR0, 1); MBAR_INIT(sb + OFF_MBAR0 + 8, 1); }
    if (tid < 32) { TCG_ALLOC(sb + OFF_TMEM, 512); TCG_RELINQ(); }
    __syncthreads();
    uint32_t tmem;
    asm volatile("ld.shared.b32 %0, [%1];" : "=r"(tmem) : "r"(sb + OFF_TMEM));

    const int lrow = tid >> 2, lq = tid & 3;

    // A tile -> TMEM (tid<128: thread = row). 64 cols hi @256, 64 cols lo @320.
#define LOADA(ii) do { \
        if (tid < 128) { \
            const uint32_t* _ah = (const uint32_t*)(g_hi + (size_t)((ii) * 128 + tid) * DD); \
            const uint32_t* _al = (const uint32_t*)(g_lo + (size_t)((ii) * 128 + tid) * DD); \
            uint32_t _wo = (uint32_t)(tid >> 5) << 21; \
            uint32_t _r[32]; \
            _Pragma("unroll") for (int _c = 0; _c < 32; _c++) _r[_c] = _ah[_c]; \
            STTM_X32(tmem + 256 + _wo, _r); \
            _Pragma("unroll") for (int _c = 0; _c < 32; _c++) _r[_c] = _ah[32 + _c]; \
            STTM_X32(tmem + 288 + _wo, _r); \
            _Pragma("unroll") for (int _c = 0; _c < 32; _c++) _r[_c] = _al[_c]; \
            STTM_X32(tmem + 320 + _wo, _r); \
            _Pragma("unroll") for (int _c = 0; _c < 32; _c++) _r[_c] = _al[32 + _c]; \
            STTM_X32(tmem + 352 + _wo, _r); \
            TCG_WAIT_ST(); \
        } } while (0)

#define CPLOADB(k) do { \
        int _jb = ((t0 + (k)) & 63) * 128; \
        const char* _sh = (const char*)(g_hi + (size_t)(_jb + lrow) * DD + lq * 32); \
        const char* _sl = (const char*)(g_lo + (size_t)(_jb + lrow) * DD + lq * 32); \
        uint32_t _bb = sb + SM_B0 + ((k) & 1) * BSTRIDE; \
        _Pragma("unroll") \
        for (int _c = 0; _c < 4; _c++) { \
            uint32_t _o = tile_off(lrow, lq * 32 + _c * 8); \
            CP_ASYNC16(_bb + _o, _sh + _c * 16); \
            CP_ASYNC16(_bb + 32768 + _o, _sl + _c * 16); \
        } \
        CP_COMMIT(); \
    } while (0)

#define LABLOAD(k) do { \
        if (tid < 128) { \
            int _jb = ((t0 + (k)) & 63) * 128; \
            ((float*)(smem + OFF_LABF))[((k) & 3) * 128 + tid] = (float)__ldg(&labels[_jb + tid]); \
        } } while (0)

#define ISSUE(k) do { \
        uint32_t _dtm = tmem + ((k) & 1) * 128; \
        uint32_t _bb = sb + SM_B0 + ((k) & 1) * BSTRIDE; \
        uint64_t _bH = DESC_BASE | ((uint64_t)(_bb >> 4) & 0x3FFF); \
        uint64_t _bL = DESC_BASE | ((uint64_t)((_bb + 32768) >> 4) & 0x3FFF); \
        const uint64_t _offs[8] = {0, 2, 4, 6, 1024, 1026, 1028, 1030}; \
        uint32_t _en = 0; \
        _Pragma("unroll") \
        for (int _k = 0; _k < 8; _k++) { mma_f16_ts(_dtm, tmem + 256 + _k * 8, _bH + _offs[_k], IDESC, _en); _en = 1; } \
        _Pragma("unroll") \
        for (int _k = 0; _k < 8; _k++) mma_f16_ts(_dtm, tmem + 256 + _k * 8, _bL + _offs[_k], IDESC, 1); \
        _Pragma("unroll") \
        for (int _k = 0; _k < 8; _k++) mma_f16_ts(_dtm, tmem + 320 + _k * 8, _bH + _offs[_k], IDESC, 1); \
        TCG_COMMIT(sb + OFF_MBAR0 + ((k) & 1) * 8); \
    } while (0)

    int aI = t0 >> 6;
    LOADA(aI);
    CPLOADB(0); LABLOAD(0);
    CPLOADB(1); LABLOAD(1);
    CP_WAIT(1);
    __syncthreads();
    if (tid == 0) { FENCE_ASYNC_SHARED(); ISSUE(0); }

    const int row = tid & 127;
    const int colBase = (tid >> 7) * 32;

    int epiI = aI;
    int gRow = epiI * 128 + row;
    unsigned long long Te = 0, Te1 = 0;

#define FLUSH() do { \
        uint32_t _l, _h; float _a; \
        UPK2(_l, _h, Te);  _a = __uint_as_float(_l) + __uint_as_float(_h); atomicAdd(&g_Z[ZOFF_TE + gRow], _a); \
        UPK2(_l, _h, Te1); _a = __uint_as_float(_l) + __uint_as_float(_h); atomicAdd(&g_Z[ZOFF_TE1 + gRow], _a); \
    } while (0)

    for (int k = 0; k < len; k++) {
        MBAR_WAIT(sb + OFF_MBAR0 + (k & 1) * 8, (k >> 1) & 1);
        TCG_FENCE_AFTER();

        const bool pref = (k + 2 < len);
        if (pref) { CPLOADB(k + 2); LABLOAD(k + 2); }
        if (k + 1 < len) {
            int ni = (t0 + k + 1) >> 6;
            if (ni != aI) { LOADA(ni); aI = ni; }   // stage k drained; safe
            if (pref) CP_WAIT(1); else CP_WAIT(0);
            __syncthreads();
            if (tid == 0) { FENCE_ASYNC_SHARED(); ISSUE(k + 1); }
        }

        const int ei = (t0 + k) >> 6;
        if (ei != epiI) {
            FLUSH();
            Te = Te1 = 0;
            epiI = ei;
            gRow = epiI * 128 + row;
        }

        uint32_t r0[32];
        LDTM_X32(r0, tmem + (k & 1) * 128 + colBase);
        TCG_WAIT_LD();

        const uint32_t lA = sb + OFF_LABF + (k & 3) * 512 + colBase * 4;
#pragma unroll
        for (int p = 0; p < 16; p++) {
            float e0 = fast_ex2(__uint_as_float(r0[2 * p]));
            float e1 = fast_ex2(__uint_as_float(r0[2 * p + 1]));
            unsigned long long pe, pw;
            PK2(pe, e0, e1);
            asm("ld.shared.b64 %0, [%1];" : "=l"(pw) : "r"(lA + p * 8));
            ADD2(Te, Te, pe);
            FMA2(Te1, pw, pe, Te1);
        }
        TCG_FENCE_BEFORE();
    }
    FLUSH();

    __syncthreads();
    if (tid == 0) { MBAR_INVAL(sb + OFF_MBAR0); MBAR_INVAL(sb + OFF_MBAR0 + 8); }
    __syncthreads();
    if (tid < 32) TCG_DEALLOC(tmem, 512);
#undef LOADA
#undef CPLOADB
#undef LABLOAD
#undef ISSUE
#undef FLUSH
#endif  // HAS_TCGEN05
}

// ---------------------------------------------------------------------------
// k_final: 32 blocks x 256 thr, one row per thread, last-block combine.
//   Td = C1*dot(f_i,fsA); Td1 = C1*dot(f_i,fs1)
//   sameE_s = lab? Te1 : Te-Te1; neg_s = Te-sameE_s; S1_s = sameE_s - 2^C1
//   posZ = (lab? Td1 : Td-Td1) - C1; cnt = lab? n1-1 : NN-n1-1
//   row = (ln2*posZ - 10*cnt - cnt*(log(neg_s)-10) - S1_s/neg_s) / cnt
// ---------------------------------------------------------------------------
__global__ __launch_bounds__(256)
void k_final(const float* __restrict__ f, const int* __restrict__ labels,
             float* __restrict__ out) {
    const int tid = threadIdx.x;
    __shared__ float fsA[DD], fs1[DD];
    __shared__ float sS[256];

    if (tid < DD) { fsA[tid] = g_Z[ZOFF_FSA + tid]; fs1[tid] = g_Z[ZOFF_FS1 + tid]; }
    __syncthreads();
    const int n1 = *(const int*)&g_Z[ZOFF_N1];

    const int i = blockIdx.x * 256 + tid;
    const int lab = labels[i];

    float dA = 0.0f, d1 = 0.0f;
    const float4* fi = (const float4*)(f + (size_t)i * DD);
#pragma unroll
    for (int c = 0; c < 32; c++) {
        float4 v = fi[c];
        dA = fmaf(v.x, fsA[4 * c + 0], dA); d1 = fmaf(v.x, fs1[4 * c + 0], d1);
        dA = fmaf(v.y, fsA[4 * c + 1], dA); d1 = fmaf(v.y, fs1[4 * c + 1], d1);
        dA = fmaf(v.z, fsA[4 * c + 2], dA); d1 = fmaf(v.z, fs1[4 * c + 2], d1);
        dA = fmaf(v.w, fsA[4 * c + 3], dA); d1 = fmaf(v.w, fs1[4 * c + 3], d1);
    }
    float Td = C1F * dA, Td1 = C1F * d1;

    float Te = g_Z[ZOFF_TE + i], Te1 = g_Z[ZOFF_TE1 + i];
    float sameE = lab ? Te1 : Te - Te1;
    float sameZ = lab ? Td1 : Td - Td1;
    float S1 = sameE - E10F;
    float posZ = sameZ - C1F;
    float neg = Te - sameE;
    float cnt = (float)(lab ? (n1 - 1) : (NN - n1 - 1));
    float posD = LN2F * posZ - 10.0f * cnt;
    float lsum = cnt * (__logf(neg) - 10.0f) + S1 / neg;
    sS[tid] = (posD - lsum) / cnt;
    __syncthreads();
    for (int k = 128; k > 0; k >>= 1) {
        if (tid < k) sS[tid] += sS[tid + k];
        __syncthreads();
    }
    if (tid == 0) {
        g_Z[ZOFF_PART + blockIdx.x] = sS[0];
        __threadfence();
        int old = atomicAdd((int*)&g_Z[ZOFF_CTR], 1);
        if (old == 31) {
            float s = 0.0f;
#pragma unroll
            for (int b = 0; b < 32; b++) s += g_Z[ZOFF_PART + b];
            out[0] = -(0.1f / 0.07f) * s / (float)NN;
        }
    }
}

// ---------------------------------------------------------------------------
extern "C" void kernel_launch(void* const* d_in, const int* in_sizes, int n_in,
                              void* d_out, int out_size) {
    const float* feats = (const float*)d_in[0];
    const int* labels = (const int*)d_in[1];
    float* out = (float*)d_out;

    void* p;
    cudaGetSymbolAddress(&p, g_Z);
    cudaMemsetAsync(p, 0, ZTOT * sizeof(float));

    cudaFuncSetAttribute(k_tiles, cudaFuncAttributeMaxDynamicSharedMemorySize, SM_TOTAL);

    k_prep<<<NN / 64, 256>>>(feats, labels);
    k_tiles<<<NCTA, NTHR, SM_TOTAL>>>(labels);
    k_final<<<32, 256>>>(feats, labels, out);
}

// round 17
// speedup vs baseline: 1.7416x; 1.5036x over previous
#include <cuda_runtime.h>
#include <cuda_bf16.h>
#include <cstdint>
#include <math.h>

#define NN 8192
#define DD 128
#define NTILE 64
#define TTOT (NTILE * NTILE)
#define NCTA 148
#define NTHR 512

#if defined(__CUDA_ARCH__) && \
    (defined(__CUDA_ARCH_FEAT_SM103_ALL) || defined(__CUDA_ARCH_FEAT_SM100_ALL) || \
     defined(__CUDA_ARCH_SPECIFIC__) || defined(__CUDA_ARCH_FAMILY_SPECIFIC__))
#define HAS_TCGEN05 1
#else
#define HAS_TCGEN05 0
#endif

#define FSCALE 3.7982826f        // sqrt(10/ln2): MMA emits z = C1*dot
#define C1F 14.4269504f          // 10*log2(e)
#define LN2F 0.69314718f
#define E10F 22026.4658f         // 2^C1 = e^10

// ---------------- scratch: bf16 hi tiles + ONE zeroed block -----------------
__device__ __nv_bfloat16 g_hi[(size_t)NN * DD];
#define ZOFF_TE   0
#define ZOFF_TE1  NN
#define ZOFF_FSA  (2 * NN)
#define ZOFF_FS1  (2 * NN + 128)
#define ZOFF_PART (2 * NN + 256)
#define ZOFF_CTR  (2 * NN + 288)
#define ZOFF_N1   (2 * NN + 289)
#define ZTOT      (2 * NN + 320)
__device__ float g_Z[ZTOT];

// ---------------- SMEM layout (k_tiles) -------------------------------------
#define OFF_TMEM 0
#define OFF_MBAR0 8
#define OFF_LABF 1024          // float[4][128] = 2 KB
#define SM_B0 4096
#define BSTRIDE 32768          // per stage: B hi only (32K)
#define SM_TOTAL (SM_B0 + 2 * BSTRIDE)   // 69632 B

#if HAS_TCGEN05
__device__ __forceinline__ uint32_t smem_u32(const void* p) {
    uint32_t a;
    asm("{ .reg .u64 t; cvta.to.shared.u64 t, %1; cvt.u32.u64 %0, t; }" : "=r"(a) : "l"(p));
    return a;
}
#define TCG_ALLOC(sm, n) asm volatile("tcgen05.alloc.cta_group::1.sync.aligned.shared::cta.b32 [%0], %1;" :: "r"(sm), "r"(n) : "memory")
#define TCG_DEALLOC(t, n) asm volatile("tcgen05.dealloc.cta_group::1.sync.aligned.b32 %0, %1;" :: "r"(t), "r"(n))
#define TCG_RELINQ() asm volatile("tcgen05.relinquish_alloc_permit.cta_group::1.sync.aligned;")
#define TCG_COMMIT(mb) asm volatile("tcgen05.commit.cta_group::1.mbarrier::arrive::one.shared::cluster.b64 [%0];" :: "r"(mb) : "memory")
#define TCG_WAIT_LD() asm volatile("tcgen05.wait::ld.sync.aligned;" ::: "memory")
#define TCG_WAIT_ST() asm volatile("tcgen05.wait::st.sync.aligned;" ::: "memory")
#define TCG_FENCE_BEFORE() asm volatile("tcgen05.fence::before_thread_sync;" ::: "memory")
#define TCG_FENCE_AFTER() asm volatile("tcgen05.fence::after_thread_sync;" ::: "memory")
#define FENCE_ASYNC_SHARED() asm volatile("fence.proxy.async.shared::cta;" ::: "memory")
#define MBAR_INIT(mb, c) asm volatile("mbarrier.init.shared.b64 [%0], %1;" :: "r"(mb), "r"(c) : "memory")
#define MBAR_INVAL(mb) asm volatile("mbarrier.inval.shared.b64 [%0];" :: "r"(mb) : "memory")
#define CP_ASYNC16(dst, src) asm volatile("cp.async.cg.shared.global [%0], [%1], 16;" :: "r"(dst), "l"(src) : "memory")
#define CP_COMMIT() asm volatile("cp.async.commit_group;" ::: "memory")
#define CP_WAIT(n) asm volatile("cp.async.wait_group %0;" :: "n"(n) : "memory")

#define MBAR_WAIT(mb, ph) do { \
    uint32_t _m = (mb); uint32_t _p = (ph); uint32_t _d; \
    asm volatile("{ .reg .pred p; mbarrier.try_wait.parity.acquire.cta.shared::cta.b64 p, [%1], %2; selp.b32 %0,1,0,p; }" \
                 : "=r"(_d) : "r"(_m), "r"(_p) : "memory"); \
    if (!_d) { \
        asm volatile("{ .reg .pred P1; WL_%=: mbarrier.try_wait.parity.acquire.cta.shared::cta.b64 P1, [%0], %1, 0x989680; @P1 bra.uni WD_%=; bra.uni WL_%=; WD_%=: }" \
                     :: "r"(_m), "r"(_p) : "memory"); \
    } } while (0)

#define LDTM_X32(r, addr) \
    asm volatile("tcgen05.ld.sync.aligned.32x32b.x32.b32 " \
        "{%0,%1,%2,%3,%4,%5,%6,%7,%8,%9,%10,%11,%12,%13,%14,%15," \
        "%16,%17,%18,%19,%20,%21,%22,%23,%24,%25,%26,%27,%28,%29,%30,%31}, [%32];" \
        : "=r"((r)[0]),"=r"((r)[1]),"=r"((r)[2]),"=r"((r)[3]),"=r"((r)[4]),"=r"((r)[5]),"=r"((r)[6]),"=r"((r)[7]), \
          "=r"((r)[8]),"=r"((r)[9]),"=r"((r)[10]),"=r"((r)[11]),"=r"((r)[12]),"=r"((r)[13]),"=r"((r)[14]),"=r"((r)[15]), \
          "=r"((r)[16]),"=r"((r)[17]),"=r"((r)[18]),"=r"((r)[19]),"=r"((r)[20]),"=r"((r)[21]),"=r"((r)[22]),"=r"((r)[23]), \
          "=r"((r)[24]),"=r"((r)[25]),"=r"((r)[26]),"=r"((r)[27]),"=r"((r)[28]),"=r"((r)[29]),"=r"((r)[30]),"=r"((r)[31]) \
        : "r"(addr))

#define STTM_X32(addr, r) \
    asm volatile("tcgen05.st.sync.aligned.32x32b.x32.b32 [%0], " \
        "{%1,%2,%3,%4,%5,%6,%7,%8,%9,%10,%11,%12,%13,%14,%15,%16," \
        "%17,%18,%19,%20,%21,%22,%23,%24,%25,%26,%27,%28,%29,%30,%31,%32};" \
        :: "r"(addr), \
           "r"((r)[0]),"r"((r)[1]),"r"((r)[2]),"r"((r)[3]),"r"((r)[4]),"r"((r)[5]),"r"((r)[6]),"r"((r)[7]), \
           "r"((r)[8]),"r"((r)[9]),"r"((r)[10]),"r"((r)[11]),"r"((r)[12]),"r"((r)[13]),"r"((r)[14]),"r"((r)[15]), \
           "r"((r)[16]),"r"((r)[17]),"r"((r)[18]),"r"((r)[19]),"r"((r)[20]),"r"((r)[21]),"r"((r)[22]),"r"((r)[23]), \
           "r"((r)[24]),"r"((r)[25]),"r"((r)[26]),"r"((r)[27]),"r"((r)[28]),"r"((r)[29]),"r"((r)[30]),"r"((r)[31]) \
        : "memory")

// TS-mode bf16 MMA: A in TMEM, B via smem descriptor
__device__ __forceinline__ void mma_f16_ts(uint32_t d, uint32_t a, uint64_t b,
                                           uint32_t idesc, uint32_t en) {
    asm volatile(
        "{\n\t.reg .pred p;\n\t"
        "setp.ne.u32 p, %5, 0;\n\t"
        "tcgen05.mma.cta_group::1.kind::f16 [%0], [%1], %2, %3, {%4,%4,%4,%4}, p;\n\t}"
        :: "r"(d), "r"(a), "l"(b), "r"(idesc), "r"(0u), "r"(en) : "memory");
}

static constexpr uint64_t DESC_BASE =
    (uint64_t(2) << 61) | (uint64_t(1) << 46) | (uint64_t(64) << 32) | (uint64_t(1) << 16);
static constexpr uint32_t IDESC =
    (1u << 4) | (1u << 7) | (1u << 10) | ((128u / 8) << 17) | ((128u / 16) << 24);

__device__ __forceinline__ uint32_t tile_off(int row, int col) {
    uint32_t off = (uint32_t)((row >> 3) + ((col >> 6) << 4)) * 1024u
                 + (uint32_t)(row & 7) * 128u + (uint32_t)(col & 63) * 2u;
    return off ^ ((off >> 3) & 0x70);
}

__device__ __forceinline__ float fast_ex2(float x) {
    float r; asm("ex2.approx.f32 %0, %1;" : "=f"(r) : "f"(x)); return r;
}

#define PK2(d, lo, hi)  asm("mov.b64 %0, {%1,%2};" : "=l"(d) : "r"(__float_as_uint(lo)), "r"(__float_as_uint(hi)))
#define UPK2(lo, hi, s) asm("mov.b64 {%0,%1}, %2;" : "=r"(lo), "=r"(hi) : "l"(s))
#define ADD2(d, a, b)   asm("add.rn.f32x2 %0, %1, %2;" : "=l"(d) : "l"(a), "l"(b))
#define FMA2(d, a, b, c) asm("fma.rn.f32x2 %0, %1, %2, %3;" : "=l"(d) : "l"(a), "l"(b), "l"(c))
#endif  // HAS_TCGEN05

// ---------------------------------------------------------------------------
// k_prep v2: 512 CTAs x 256 thr; 16 rows/CTA. Converts FSCALE*x -> bf16 hi,
// and accumulates column sums fsA (all rows) / fs1 (label-weighted) via a
// shared-memory matrix reduce (no atomics contention). n1 via one atomic/CTA.
// ---------------------------------------------------------------------------
__global__ __launch_bounds__(256)
void k_prep(const float* __restrict__ f, const int* __restrict__ labels) {
    __shared__ float sV[16][128];
    __shared__ float sW[16][128];
    const int tid = threadIdx.x;
    const int rb = blockIdx.x * 16;
    const int r = tid >> 4;            // local row 0..15
    const int cg = (tid & 15) * 8;     // col base
    const int row = rb + r;

    const float w = (float)labels[row];
    const float4* fp = (const float4*)(f + (size_t)row * DD + cg);
    float4 v0 = fp[0], v1 = fp[1];

    // hi conversion (scaled)
    float s0 = v0.x * FSCALE, s1 = v0.y * FSCALE, s2 = v0.z * FSCALE, s3 = v0.w * FSCALE;
    float s4 = v1.x * FSCALE, s5 = v1.y * FSCALE, s6 = v1.z * FSCALE, s7 = v1.w * FSCALE;
    __nv_bfloat162 h01(__float2bfloat16(s0), __float2bfloat16(s1));
    __nv_bfloat162 h23(__float2bfloat16(s2), __float2bfloat16(s3));
    __nv_bfloat162 h45(__float2bfloat16(s4), __float2bfloat16(s5));
    __nv_bfloat162 h67(__float2bfloat16(s6), __float2bfloat16(s7));
    uint4 hp;
    hp.x = *(uint32_t*)&h01; hp.y = *(uint32_t*)&h23;
    hp.z = *(uint32_t*)&h45; hp.w = *(uint32_t*)&h67;
    *(uint4*)(g_hi + (size_t)row * DD + cg) = hp;

    // raw column partials (unscaled feats)
    *(float4*)&sV[r][cg]     = v0;
    *(float4*)&sV[r][cg + 4] = v1;
    float4 w0 = make_float4(w * v0.x, w * v0.y, w * v0.z, w * v0.w);
    float4 w1 = make_float4(w * v1.x, w * v1.y, w * v1.z, w * v1.w);
    *(float4*)&sW[r][cg]     = w0;
    *(float4*)&sW[r][cg + 4] = w1;
    __syncthreads();

    if (tid < 128) {
        float a = 0.0f, b = 0.0f;
#pragma unroll
        for (int rr = 0; rr < 16; rr++) { a += sV[rr][tid]; b += sW[rr][tid]; }
        atomicAdd(&g_Z[ZOFF_FSA + tid], a);
        atomicAdd(&g_Z[ZOFF_FS1 + tid], b);
    }
    if (tid == 0) {
        int s = 0;
#pragma unroll
        for (int rr = 0; rr < 16; rr++) s += labels[rb + rr];
        atomicAdd((int*)&g_Z[ZOFF_N1], s);
    }
}

// ---------------------------------------------------------------------------
// k_tiles: persistent 148-CTA schedule, 512 thr, hi-only TS-mode MMA
// (8 K16 dispatches/tile), cp.async 2-ahead B, ping-pong D in TMEM.
// Epilogue: Te = sum 2^z, Te1 = sum w*2^z per row.
// TMEM: D0 @0, D1 @128, A hi @256 (64 cols).
// ---------------------------------------------------------------------------
__global__ __launch_bounds__(NTHR, 1)
void k_tiles(const int* __restrict__ labels) {
#if HAS_TCGEN05
    extern __shared__ char smem[];
    const uint32_t sb = smem_u32(smem);
    const int tid = threadIdx.x;
    const int cta = blockIdx.x;

    const int t0 = (TTOT * cta) / NCTA;
    const int t1 = (TTOT * (cta + 1)) / NCTA;
    const int len = t1 - t0;

    if (tid == 0) { MBAR_INIT(sb + OFF_MBAR0, 1); MBAR_INIT(sb + OFF_MBAR0 + 8, 1); }
    if (tid < 32) { TCG_ALLOC(sb + OFF_TMEM, 512); TCG_RELINQ(); }
    __syncthreads();
    uint32_t tmem;
    asm volatile("ld.shared.b32 %0, [%1];" : "=r"(tmem) : "r"(sb + OFF_TMEM));

    const int lrow = tid >> 2, lq = tid & 3;

#define LOADA(ii) do { \
        if (tid < 128) { \
            const uint32_t* _ah = (const uint32_t*)(g_hi + (size_t)((ii) * 128 + tid) * DD); \
            uint32_t _wo = (uint32_t)(tid >> 5) << 21; \
            uint32_t _r[32]; \
            _Pragma("unroll") for (int _c = 0; _c < 32; _c++) _r[_c] = _ah[_c]; \
            STTM_X32(tmem + 256 + _wo, _r); \
            _Pragma("unroll") for (int _c = 0; _c < 32; _c++) _r[_c] = _ah[32 + _c]; \
            STTM_X32(tmem + 288 + _wo, _r); \
            TCG_WAIT_ST(); \
        } } while (0)

#define CPLOADB(k) do { \
        int _jb = ((t0 + (k)) & 63) * 128; \
        const char* _sh = (const char*)(g_hi + (size_t)(_jb + lrow) * DD + lq * 32); \
        uint32_t _bb = sb + SM_B0 + ((k) & 1) * BSTRIDE; \
        _Pragma("unroll") \
        for (int _c = 0; _c < 4; _c++) { \
            uint32_t _o = tile_off(lrow, lq * 32 + _c * 8); \
            CP_ASYNC16(_bb + _o, _sh + _c * 16); \
        } \
        CP_COMMIT(); \
    } while (0)

#define LABLOAD(k) do { \
        if (tid < 128) { \
            int _jb = ((t0 + (k)) & 63) * 128; \
            ((float*)(smem + OFF_LABF))[((k) & 3) * 128 + tid] = (float)__ldg(&labels[_jb + tid]); \
        } } while (0)

#define ISSUE(k) do { \
        uint32_t _dtm = tmem + ((k) & 1) * 128; \
        uint32_t _bb = sb + SM_B0 + ((k) & 1) * BSTRIDE; \
        uint64_t _bH = DESC_BASE | ((uint64_t)(_bb >> 4) & 0x3FFF); \
        const uint64_t _offs[8] = {0, 2, 4, 6, 1024, 1026, 1028, 1030}; \
        uint32_t _en = 0; \
        _Pragma("unroll") \
        for (int _k = 0; _k < 8; _k++) { mma_f16_ts(_dtm, tmem + 256 + _k * 8, _bH + _offs[_k], IDESC, _en); _en = 1; } \
        TCG_COMMIT(sb + OFF_MBAR0 + ((k) & 1) * 8); \
    } while (0)

    int aI = t0 >> 6;
    LOADA(aI);
    CPLOADB(0); LABLOAD(0);
    CPLOADB(1); LABLOAD(1);
    CP_WAIT(1);
    __syncthreads();
    if (tid == 0) { FENCE_ASYNC_SHARED(); ISSUE(0); }

    const int row = tid & 127;
    const int colBase = (tid >> 7) * 32;

    int epiI = aI;
    int gRow = epiI * 128 + row;
    unsigned long long Te = 0, Te1 = 0;

#define FLUSH() do { \
        uint32_t _l, _h; float _a; \
        UPK2(_l, _h, Te);  _a = __uint_as_float(_l) + __uint_as_float(_h); atomicAdd(&g_Z[ZOFF_TE + gRow], _a); \
        UPK2(_l, _h, Te1); _a = __uint_as_float(_l) + __uint_as_float(_h); atomicAdd(&g_Z[ZOFF_TE1 + gRow], _a); \
    } while (0)

    for (int k = 0; k < len; k++) {
        MBAR_WAIT(sb + OFF_MBAR0 + (k & 1) * 8, (k >> 1) & 1);
        TCG_FENCE_AFTER();

        const bool pref = (k + 2 < len);
        if (pref) { CPLOADB(k + 2); LABLOAD(k + 2); }
        if (k + 1 < len) {
            int ni = (t0 + k + 1) >> 6;
            if (ni != aI) { LOADA(ni); aI = ni; }
            if (pref) CP_WAIT(1); else CP_WAIT(0);
            __syncthreads();
            if (tid == 0) { FENCE_ASYNC_SHARED(); ISSUE(k + 1); }
        }

        const int ei = (t0 + k) >> 6;
        if (ei != epiI) {
            FLUSH();
            Te = Te1 = 0;
            epiI = ei;
            gRow = epiI * 128 + row;
        }

        uint32_t r0[32];
        LDTM_X32(r0, tmem + (k & 1) * 128 + colBase);
        TCG_WAIT_LD();

        const uint32_t lA = sb + OFF_LABF + (k & 3) * 512 + colBase * 4;
#pragma unroll
        for (int p = 0; p < 16; p++) {
            float e0 = fast_ex2(__uint_as_float(r0[2 * p]));
            float e1 = fast_ex2(__uint_as_float(r0[2 * p + 1]));
            unsigned long long pe, pw;
            PK2(pe, e0, e1);
            asm("ld.shared.b64 %0, [%1];" : "=l"(pw) : "r"(lA + p * 8));
            ADD2(Te, Te, pe);
            FMA2(Te1, pw, pe, Te1);
        }
        TCG_FENCE_BEFORE();
    }
    FLUSH();

    __syncthreads();
    if (tid == 0) { MBAR_INVAL(sb + OFF_MBAR0); MBAR_INVAL(sb + OFF_MBAR0 + 8); }
    __syncthreads();
    if (tid < 32) TCG_DEALLOC(tmem, 512);
#undef LOADA
#undef CPLOADB
#undef LABLOAD
#undef ISSUE
#undef FLUSH
#endif  // HAS_TCGEN05
}

// ---------------------------------------------------------------------------
// k_final: 32 blocks x 256 thr, one row per thread, last-block combine.
//   Td = C1*dot(f_i,fsA); Td1 = C1*dot(f_i,fs1)   [exact fp32 rank-1]
//   sameE_s = lab? Te1 : Te-Te1; neg_s = Te-sameE_s; S1_s = sameE_s - 2^C1
//   posZ = (lab? Td1 : Td-Td1) - C1; cnt = lab? n1-1 : NN-n1-1
//   row = (ln2*posZ - 10*cnt - cnt*(log(neg_s)-10) - S1_s/neg_s) / cnt
// ---------------------------------------------------------------------------
__global__ __launch_bounds__(256)
void k_final(const float* __restrict__ f, const int* __restrict__ labels,
             float* __restrict__ out) {
    const int tid = threadIdx.x;
    __shared__ float fsA[DD], fs1[DD];
    __shared__ float sS[256];

    if (tid < DD) { fsA[tid] = g_Z[ZOFF_FSA + tid]; fs1[tid] = g_Z[ZOFF_FS1 + tid]; }
    __syncthreads();
    const int n1 = *(const int*)&g_Z[ZOFF_N1];

    const int i = blockIdx.x * 256 + tid;
    const int lab = labels[i];

    float dA = 0.0f, d1 = 0.0f;
    const float4* fi = (const float4*)(f + (size_t)i * DD);
#pragma unroll
    for (int c = 0; c < 32; c++) {
        float4 v = fi[c];
        dA = fmaf(v.x, fsA[4 * c + 0], dA); d1 = fmaf(v.x, fs1[4 * c + 0], d1);
        dA = fmaf(v.y, fsA[4 * c + 1], dA); d1 = fmaf(v.y, fs1[4 * c + 1], d1);
        dA = fmaf(v.z, fsA[4 * c + 2], dA); d1 = fmaf(v.z, fs1[4 * c + 2], d1);
        dA = fmaf(v.w, fsA[4 * c + 3], dA); d1 = fmaf(v.w, fs1[4 * c + 3], d1);
    }
    float Td = C1F * dA, Td1 = C1F * d1;

    float Te = g_Z[ZOFF_TE + i], Te1 = g_Z[ZOFF_TE1 + i];
    float sameE = lab ? Te1 : Te - Te1;
    float sameZ = lab ? Td1 : Td - Td1;
    float S1 = sameE - E10F;
    float posZ = sameZ - C1F;
    float neg = Te - sameE;
    float cnt = (float)(lab ? (n1 - 1) : (NN - n1 - 1));
    float posD = LN2F * posZ - 10.0f * cnt;
    float lsum = cnt * (__logf(neg) - 10.0f) + S1 / neg;
    sS[tid] = (posD - lsum) / cnt;
    __syncthreads();
    for (int k = 128; k > 0; k >>= 1) {
        if (tid < k) sS[tid] += sS[tid + k];
        __syncthreads();
    }
    if (tid == 0) {
        g_Z[ZOFF_PART + blockIdx.x] = sS[0];
        __threadfence();
        int old = atomicAdd((int*)&g_Z[ZOFF_CTR], 1);
        if (old == 31) {
            float s = 0.0f;
#pragma unroll
            for (int b = 0; b < 32; b++) s += g_Z[ZOFF_PART + b];
            out[0] = -(0.1f / 0.07f) * s / (float)NN;
        }
    }
}

// ---------------------------------------------------------------------------
extern "C" void kernel_launch(void* const* d_in, const int* in_sizes, int n_in,
                              void* d_out, int out_size) {
    const float* feats = (const float*)d_in[0];
    const int* labels = (const int*)d_in[1];
    float* out = (float*)d_out;

    void* p;
    cudaGetSymbolAddress(&p, g_Z);
    cudaMemsetAsync(p, 0, ZTOT * sizeof(float));

    cudaFuncSetAttribute(k_tiles, cudaFuncAttributeMaxDynamicSharedMemorySize, SM_TOTAL);

    k_prep<<<NN / 16, 256>>>(feats, labels);
    k_tiles<<<NCTA, NTHR, SM_TOTAL>>>(labels);
    k_final<<<32, 256>>>(feats, labels, out);
}